// round 3
// baseline (speedup 1.0000x reference)
#include <cuda_runtime.h>
#include <cuda_bf16.h>
#include <math.h>

#define A_   128
#define D_   128
#define DM1  127
#define MAXB 64

// T probabilities, bf16, laid out [d][warp(8)][lane(32)][kk(16)] in uint2 units
// so each lane's 16 values per (d,warp) are one contiguous 128B run.
__device__ uint2  g_T[(size_t)DM1 * A_ * A_ / 4];
// Emission table: {sigmoid(l), sigmoid(-l)} = {p(x=1|a), p(x=0|a)} per (d,j).
__device__ float2 g_S2[D_ * A_];
// Initial-state probabilities (softmax of u_log_p_a1).
__device__ float  g_pa1[A_];

// ---------------------------------------------------------------------------
// Prep A: row softmax of u_log_transition -> g_T (bf16, permuted layout).
// One warp per row (d,k). lane covers j-quad 4*lane..4*lane+3.
// ---------------------------------------------------------------------------
__global__ void k_prepT(const float* __restrict__ u) {
    int w = threadIdx.x >> 5, lane = threadIdx.x & 31;
    int row = blockIdx.x * 8 + w;
    if (row >= DM1 * A_) return;
    float4 v4 = reinterpret_cast<const float4*>(u)[(size_t)row * 32 + lane];
    float m = fmaxf(fmaxf(v4.x, v4.y), fmaxf(v4.z, v4.w));
    #pragma unroll
    for (int o = 16; o > 0; o >>= 1) m = fmaxf(m, __shfl_xor_sync(0xffffffffu, m, o));
    float e0 = __expf(v4.x - m), e1 = __expf(v4.y - m);
    float e2 = __expf(v4.z - m), e3 = __expf(v4.w - m);
    float s = e0 + e1 + e2 + e3;
    #pragma unroll
    for (int o = 16; o > 0; o >>= 1) s += __shfl_xor_sync(0xffffffffu, s, o);
    float inv = 1.0f / s;
    __nv_bfloat162 p0 = __floats2bfloat162_rn(e0 * inv, e1 * inv);
    __nv_bfloat162 p1 = __floats2bfloat162_rn(e2 * inv, e3 * inv);
    uint2 ov;
    ov.x = *reinterpret_cast<unsigned int*>(&p0);
    ov.y = *reinterpret_cast<unsigned int*>(&p1);
    int d = row >> 7;          // row / A_
    int k = row & (A_ - 1);    // row % A_
    size_t idx = ((((size_t)d * 8 + (k >> 4)) * 32 + lane) * 16) + (k & 15);
    g_T[idx] = ov;
}

// ---------------------------------------------------------------------------
// Prep B: emission sigmoid table.
// ---------------------------------------------------------------------------
__global__ void k_prepS(const float* __restrict__ lpx) {
    int i = blockIdx.x * 256 + threadIdx.x;
    if (i < D_ * A_) {
        float l = lpx[i];
        g_S2[i] = make_float2(1.0f / (1.0f + __expf(-l)),
                              1.0f / (1.0f + __expf(l)));
    }
}

// ---------------------------------------------------------------------------
// Prep C: softmax of u_log_p_a1 -> g_pa1 (probs); writes log_p_a1 output tail.
// ---------------------------------------------------------------------------
__global__ void k_pa1(const float* __restrict__ u, float* __restrict__ out,
                      int base, int out_size) {
    __shared__ float sred[4];
    int t = threadIdx.x, lane = t & 31, w = t >> 5;
    float v = u[t];
    float m = v;
    #pragma unroll
    for (int o = 16; o > 0; o >>= 1) m = fmaxf(m, __shfl_xor_sync(0xffffffffu, m, o));
    if (lane == 0) sred[w] = m;
    __syncthreads();
    m = fmaxf(fmaxf(sred[0], sred[1]), fmaxf(sred[2], sred[3]));
    __syncthreads();
    float e = __expf(v - m);
    float s = e;
    #pragma unroll
    for (int o = 16; o > 0; o >>= 1) s += __shfl_xor_sync(0xffffffffu, s, o);
    if (lane == 0) sred[w] = s;
    __syncthreads();
    s = sred[0] + sred[1] + sred[2] + sred[3];
    float lp = v - m - logf(s);
    g_pa1[t] = __expf(lp);
    int idx = base + t;
    if (idx < out_size) out[idx] = lp;
}

// ---------------------------------------------------------------------------
// Main forward recurrence. grid = B, block = 256 (8 warps), 1 CTA/SM.
// Warp w owns k/j slice [16w,16w+16); lane l<16 holds v[16w+l] in a register.
// T register-double-buffered (uint4[8] per buffer); one barrier per step.
// ---------------------------------------------------------------------------
__global__ void __launch_bounds__(256, 1) k_forward(const float* __restrict__ x,
                                                    float* __restrict__ out,
                                                    int out_size) {
    const int b = blockIdx.x;
    const int t = threadIdx.x;
    const int w = t >> 5, lane = t & 31;
    const int kb = w * 16;

    __shared__ float part[2][8][A_];
    __shared__ float s_red[8];
    __shared__ float sx[D_];

    if (t < D_) sx[t] = x[b * D_ + t];
    __syncthreads();

    float v_reg = 0.f, acc = 0.f, e_pref = 0.f;
    if (lane < 16) {
        int j = kb + lane;
        float2 s0 = g_S2[j];
        v_reg = ((sx[0] > 0.5f) ? s0.x : s0.y) * g_pa1[j];
        float2 s1 = g_S2[A_ + j];
        e_pref = (sx[1] > 0.5f) ? s1.x : s1.y;
    }

    // per-(d,warp,lane) contiguous T: 16 uint2 = 8 uint4
    const uint4* Tbase = reinterpret_cast<const uint4*>(g_T) +
                         ((size_t)w * 32 + lane) * 8;

    uint4 TA[8], TB[8];
    {
        const uint4* tp = Tbase;   // d-matrix 0
        #pragma unroll
        for (int q = 0; q < 8; ++q) TA[q] = tp[q];
    }
    int buf = 0;

#define PREFETCH_T(DST, DMAT) do {                                          \
        const uint4* _tp = Tbase + (size_t)(DMAT) * 2048;                   \
        _Pragma("unroll")                                                   \
        for (int q = 0; q < 8; ++q) (DST)[q] = _tp[q];                      \
    } while (0)

#define STEP(DD, TARR) do {                                                 \
        float ax = 0.f, ay = 0.f, az = 0.f, a4 = 0.f;                       \
        _Pragma("unroll")                                                   \
        for (int q = 0; q < 8; ++q) {                                       \
            float vk0 = __shfl_sync(0xffffffffu, v_reg, 2 * q);             \
            float vk1 = __shfl_sync(0xffffffffu, v_reg, 2 * q + 1);         \
            uint4 r = (TARR)[q];                                            \
            ax = fmaf(vk0, __uint_as_float(r.x << 16), ax);                 \
            ay = fmaf(vk0, __uint_as_float(r.x & 0xffff0000u), ay);         \
            az = fmaf(vk0, __uint_as_float(r.y << 16), az);                 \
            a4 = fmaf(vk0, __uint_as_float(r.y & 0xffff0000u), a4);         \
            ax = fmaf(vk1, __uint_as_float(r.z << 16), ax);                 \
            ay = fmaf(vk1, __uint_as_float(r.z & 0xffff0000u), ay);         \
            az = fmaf(vk1, __uint_as_float(r.w << 16), az);                 \
            a4 = fmaf(vk1, __uint_as_float(r.w & 0xffff0000u), a4);         \
        }                                                                   \
        *reinterpret_cast<float4*>(&part[buf][w][4 * lane]) =               \
            make_float4(ax, ay, az, a4);                                    \
        __syncthreads();                                                    \
        if (lane < 16) {                                                    \
            int j = kb + lane;                                              \
            float p0 = part[buf][0][j], p1 = part[buf][1][j];               \
            float p2 = part[buf][2][j], p3 = part[buf][3][j];               \
            float p4 = part[buf][4][j], p5 = part[buf][5][j];               \
            float p6 = part[buf][6][j], p7 = part[buf][7][j];               \
            float s = ((p0 + p1) + (p2 + p3)) + ((p4 + p5) + (p6 + p7));    \
            v_reg = s * e_pref;                                             \
            int dn = ((DD) + 1 < D_) ? (DD) + 1 : (DD);                     \
            float2 sn = g_S2[dn * A_ + j];                                  \
            e_pref = (sx[dn] > 0.5f) ? sn.x : sn.y;                         \
        }                                                                   \
        if (((DD) & 15) == 15) {                                            \
            float m = v_reg;                                                \
            m = fmaxf(m, __shfl_xor_sync(0xffffffffu, m, 8, 16));           \
            m = fmaxf(m, __shfl_xor_sync(0xffffffffu, m, 4, 16));           \
            m = fmaxf(m, __shfl_xor_sync(0xffffffffu, m, 2, 16));           \
            m = fmaxf(m, __shfl_xor_sync(0xffffffffu, m, 1, 16));           \
            if (lane == 0) s_red[w] = m;                                    \
            __syncthreads();                                                \
            float mm = fmaxf(                                               \
                fmaxf(fmaxf(s_red[0], s_red[1]), fmaxf(s_red[2], s_red[3])),\
                fmaxf(fmaxf(s_red[4], s_red[5]), fmaxf(s_red[6], s_red[7])));\
            float inv = 1.0f / mm;                                          \
            if (lane < 16) v_reg *= inv;                                    \
            acc += __logf(mm);                                              \
        }                                                                   \
        buf ^= 1;                                                           \
    } while (0)

    // steps d = 1 .. 126 in pairs, double-buffered T
    for (int i = 1; i < DM1; i += 2) {
        PREFETCH_T(TB, i);                           // T[i] used at step i+1
        STEP(i, TA);
        PREFETCH_T(TA, (i + 1 < DM1) ? (i + 1) : i); // T[i+1] used at step i+2
        STEP(i + 1, TB);
    }
    // final step d = 127 uses T[126] (in TA)
    STEP(DM1, TA);

#undef STEP
#undef PREFETCH_T

    // final: log_px[b] = acc + log(sum_j v[j])
    float sv = (lane < 16) ? v_reg : 0.f;
    sv += __shfl_xor_sync(0xffffffffu, sv, 8, 16);
    sv += __shfl_xor_sync(0xffffffffu, sv, 4, 16);
    sv += __shfl_xor_sync(0xffffffffu, sv, 2, 16);
    sv += __shfl_xor_sync(0xffffffffu, sv, 1, 16);
    if (lane == 0) s_red[w] = sv;
    __syncthreads();
    float tot = (s_red[0] + s_red[1]) + (s_red[2] + s_red[3])
              + (s_red[4] + s_red[5]) + (s_red[6] + s_red[7]);
    float res = acc + __logf(tot);
    if (t < A_) {
        int idx = b * A_ + t;
        if (idx < out_size) out[idx] = res;
    }
}

// ---------------------------------------------------------------------------
extern "C" void kernel_launch(void* const* d_in, const int* in_sizes, int n_in,
                              void* d_out, int out_size) {
    const float* x     = (const float*)d_in[0];   // [B, D]
    const float* u_pa1 = (const float*)d_in[1];   // [1,1,1,A]
    const float* u_T   = (const float*)d_in[2];   // [D-1, A, A]
    const float* lpx   = (const float*)d_in[3];   // [1, D, 1, A]
    float* out = (float*)d_out;

    int B = in_sizes[0] / D_;
    if (B > MAXB) B = MAXB;

    k_prepT<<<(DM1 * A_ + 7) / 8, 256>>>(u_T);
    k_prepS<<<(D_ * A_ + 255) / 256, 256>>>(lpx);
    k_pa1<<<1, 128>>>(u_pa1, out, B * A_, out_size);

    k_forward<<<B, 256>>>(x, out, out_size);
}

// round 4
// speedup vs baseline: 2.0068x; 2.0068x over previous
#include <cuda_runtime.h>
#include <cuda_bf16.h>
#include <math.h>

#define A_   128
#define D_   128
#define DM1  127
#define MAXB 64

// T probabilities, bf16. Layout (uint4 units):
//   idx4 = (d*64 + w*8 + q)*32 + lane
// holding {T[kb+2q][4l..4l+3], T[kb+2q+1][4l..4l+3]} where kb = 16*w.
// Consecutive lanes -> consecutive uint4: every warp LDG.128 is one 512B run.
__device__ uint2  g_T[(size_t)DM1 * A_ * A_ / 4];   // viewed as uint4[...]
// Emission table: {sigmoid(l), sigmoid(-l)} = {p(x=1|a), p(x=0|a)} per (d,j).
__device__ float2 g_S2[D_ * A_];
// Initial-state probabilities (softmax of u_log_p_a1).
__device__ float  g_pa1[A_];

// ---------------------------------------------------------------------------
// Prep A: row softmax of u_log_transition -> g_T (bf16, packed layout above).
// One warp per (d,k) row; lane covers j-quad 4*lane..4*lane+3.
// ---------------------------------------------------------------------------
__global__ void k_prepT(const float* __restrict__ u) {
    int w = threadIdx.x >> 5, lane = threadIdx.x & 31;
    int row = blockIdx.x * 8 + w;
    if (row >= DM1 * A_) return;
    float4 v4 = reinterpret_cast<const float4*>(u)[(size_t)row * 32 + lane];
    float m = fmaxf(fmaxf(v4.x, v4.y), fmaxf(v4.z, v4.w));
    #pragma unroll
    for (int o = 16; o > 0; o >>= 1) m = fmaxf(m, __shfl_xor_sync(0xffffffffu, m, o));
    float e0 = __expf(v4.x - m), e1 = __expf(v4.y - m);
    float e2 = __expf(v4.z - m), e3 = __expf(v4.w - m);
    float s = e0 + e1 + e2 + e3;
    #pragma unroll
    for (int o = 16; o > 0; o >>= 1) s += __shfl_xor_sync(0xffffffffu, s, o);
    float inv = 1.0f / s;
    __nv_bfloat162 p0 = __floats2bfloat162_rn(e0 * inv, e1 * inv);  // lo=j0, hi=j1
    __nv_bfloat162 p1 = __floats2bfloat162_rn(e2 * inv, e3 * inv);  // lo=j2, hi=j3
    uint2 ov;
    ov.x = *reinterpret_cast<unsigned int*>(&p0);
    ov.y = *reinterpret_cast<unsigned int*>(&p1);
    int d  = row >> 7;           // row / A_
    int k  = row & (A_ - 1);     // row % A_
    int wt = k >> 4;             // owning warp
    int kk = k & 15;
    // uint2 index: each uint4 = 2 uint2; half kk&1 selects which k of the pair
    size_t i2 = (((size_t)d * 64 + wt * 8 + (kk >> 1)) * 32 + lane) * 2 + (kk & 1);
    g_T[i2] = ov;
}

// ---------------------------------------------------------------------------
// Prep B: emission sigmoid table.
// ---------------------------------------------------------------------------
__global__ void k_prepS(const float* __restrict__ lpx) {
    int i = blockIdx.x * 256 + threadIdx.x;
    if (i < D_ * A_) {
        float l = lpx[i];
        g_S2[i] = make_float2(1.0f / (1.0f + __expf(-l)),
                              1.0f / (1.0f + __expf(l)));
    }
}

// ---------------------------------------------------------------------------
// Prep C: softmax of u_log_p_a1 -> g_pa1 (probs); writes log_p_a1 output tail.
// ---------------------------------------------------------------------------
__global__ void k_pa1(const float* __restrict__ u, float* __restrict__ out,
                      int base, int out_size) {
    __shared__ float sred[4];
    int t = threadIdx.x, lane = t & 31, w = t >> 5;
    float v = u[t];
    float m = v;
    #pragma unroll
    for (int o = 16; o > 0; o >>= 1) m = fmaxf(m, __shfl_xor_sync(0xffffffffu, m, o));
    if (lane == 0) sred[w] = m;
    __syncthreads();
    m = fmaxf(fmaxf(sred[0], sred[1]), fmaxf(sred[2], sred[3]));
    __syncthreads();
    float e = __expf(v - m);
    float s = e;
    #pragma unroll
    for (int o = 16; o > 0; o >>= 1) s += __shfl_xor_sync(0xffffffffu, s, o);
    if (lane == 0) sred[w] = s;
    __syncthreads();
    s = sred[0] + sred[1] + sred[2] + sred[3];
    float lp = v - m - logf(s);
    g_pa1[t] = __expf(lp);
    int idx = base + t;
    if (idx < out_size) out[idx] = lp;
}

// ---------------------------------------------------------------------------
// Main forward recurrence. grid = B, block = 256 (8 warps), 1 CTA/SM.
// Warp w owns k/j slice [16w,16w+16); lane l<16 holds v[16w+l] in a register.
// T register-double-buffered (uint4[8] per buffer), coalesced LDG.128;
// one barrier per step; rescale every 16 steps, computed redundantly.
// ---------------------------------------------------------------------------
__global__ void __launch_bounds__(256, 1) k_forward(const float* __restrict__ x,
                                                    float* __restrict__ out,
                                                    int out_size) {
    const int b = blockIdx.x;
    const int t = threadIdx.x;
    const int w = t >> 5, lane = t & 31;
    const int kb = w * 16;

    __shared__ float part[2][8][A_];
    __shared__ float s_red[8];
    __shared__ float sx[D_];

    if (t < D_) sx[t] = x[b * D_ + t];
    __syncthreads();

    float v_reg = 0.f, acc = 0.f, e_pref = 0.f;
    if (lane < 16) {
        int j = kb + lane;
        float2 s0 = g_S2[j];
        v_reg = ((sx[0] > 0.5f) ? s0.x : s0.y) * g_pa1[j];
        float2 s1 = g_S2[A_ + j];
        e_pref = (sx[1] > 0.5f) ? s1.x : s1.y;
    }

    // per-(warp) base in uint4 units; +d*2048 per matrix; +q*32 per pair-row
    const uint4* Tbase = reinterpret_cast<const uint4*>(g_T) +
                         (size_t)w * 8 * 32 + lane;

    uint4 TA[8], TB[8];
    {
        #pragma unroll
        for (int q = 0; q < 8; ++q) TA[q] = Tbase[q * 32];   // d-matrix 0
    }
    int buf = 0;

#define PREFETCH_T(DST, DMAT) do {                                          \
        const uint4* _tp = Tbase + (size_t)(DMAT) * 2048;                   \
        _Pragma("unroll")                                                   \
        for (int q = 0; q < 8; ++q) (DST)[q] = _tp[q * 32];                 \
    } while (0)

#define STEP(DD, TARR) do {                                                 \
        float ax = 0.f, ay = 0.f, az = 0.f, a4 = 0.f;                       \
        _Pragma("unroll")                                                   \
        for (int q = 0; q < 8; ++q) {                                       \
            float vk0 = __shfl_sync(0xffffffffu, v_reg, 2 * q);             \
            float vk1 = __shfl_sync(0xffffffffu, v_reg, 2 * q + 1);         \
            uint4 r = (TARR)[q];                                            \
            ax = fmaf(vk0, __uint_as_float(r.x << 16), ax);                 \
            ay = fmaf(vk0, __uint_as_float(r.x & 0xffff0000u), ay);         \
            az = fmaf(vk0, __uint_as_float(r.y << 16), az);                 \
            a4 = fmaf(vk0, __uint_as_float(r.y & 0xffff0000u), a4);         \
            ax = fmaf(vk1, __uint_as_float(r.z << 16), ax);                 \
            ay = fmaf(vk1, __uint_as_float(r.z & 0xffff0000u), ay);         \
            az = fmaf(vk1, __uint_as_float(r.w << 16), az);                 \
            a4 = fmaf(vk1, __uint_as_float(r.w & 0xffff0000u), a4);         \
        }                                                                   \
        *reinterpret_cast<float4*>(&part[buf][w][4 * lane]) =               \
            make_float4(ax, ay, az, a4);                                    \
        __syncthreads();                                                    \
        if (lane < 16) {                                                    \
            int j = kb + lane;                                              \
            float p0 = part[buf][0][j], p1 = part[buf][1][j];               \
            float p2 = part[buf][2][j], p3 = part[buf][3][j];               \
            float p4 = part[buf][4][j], p5 = part[buf][5][j];               \
            float p6 = part[buf][6][j], p7 = part[buf][7][j];               \
            float s = ((p0 + p1) + (p2 + p3)) + ((p4 + p5) + (p6 + p7));    \
            v_reg = s * e_pref;                                             \
            int dn = ((DD) + 1 < D_) ? (DD) + 1 : (DD);                     \
            float2 sn = g_S2[dn * A_ + j];                                  \
            e_pref = (sx[dn] > 0.5f) ? sn.x : sn.y;                         \
        }                                                                   \
        if (((DD) & 15) == 15) {                                            \
            float m = v_reg;                                                \
            m = fmaxf(m, __shfl_xor_sync(0xffffffffu, m, 8, 16));           \
            m = fmaxf(m, __shfl_xor_sync(0xffffffffu, m, 4, 16));           \
            m = fmaxf(m, __shfl_xor_sync(0xffffffffu, m, 2, 16));           \
            m = fmaxf(m, __shfl_xor_sync(0xffffffffu, m, 1, 16));           \
            if (lane == 0) s_red[w] = m;                                    \
            __syncthreads();                                                \
            float mm = fmaxf(                                               \
                fmaxf(fmaxf(s_red[0], s_red[1]), fmaxf(s_red[2], s_red[3])),\
                fmaxf(fmaxf(s_red[4], s_red[5]), fmaxf(s_red[6], s_red[7])));\
            float inv = 1.0f / mm;                                          \
            if (lane < 16) v_reg *= inv;                                    \
            acc += __logf(mm);                                              \
        }                                                                   \
        buf ^= 1;                                                           \
    } while (0)

    // steps d = 1 .. 126 in pairs, double-buffered T
    for (int i = 1; i < DM1; i += 2) {
        PREFETCH_T(TB, i);                           // T[i] used at step i+1
        STEP(i, TA);
        PREFETCH_T(TA, (i + 1 < DM1) ? (i + 1) : i); // T[i+1] used at step i+2
        STEP(i + 1, TB);
    }
    // final step d = 127 uses T[126] (in TA)
    STEP(DM1, TA);

#undef STEP
#undef PREFETCH_T

    // final: log_px[b] = acc + log(sum_j v[j])
    float sv = (lane < 16) ? v_reg : 0.f;
    sv += __shfl_xor_sync(0xffffffffu, sv, 8, 16);
    sv += __shfl_xor_sync(0xffffffffu, sv, 4, 16);
    sv += __shfl_xor_sync(0xffffffffu, sv, 2, 16);
    sv += __shfl_xor_sync(0xffffffffu, sv, 1, 16);
    if (lane == 0) s_red[w] = sv;
    __syncthreads();
    float tot = (s_red[0] + s_red[1]) + (s_red[2] + s_red[3])
              + (s_red[4] + s_red[5]) + (s_red[6] + s_red[7]);
    float res = acc + __logf(tot);
    if (t < A_) {
        int idx = b * A_ + t;
        if (idx < out_size) out[idx] = res;
    }
}

// ---------------------------------------------------------------------------
extern "C" void kernel_launch(void* const* d_in, const int* in_sizes, int n_in,
                              void* d_out, int out_size) {
    const float* x     = (const float*)d_in[0];   // [B, D]
    const float* u_pa1 = (const float*)d_in[1];   // [1,1,1,A]
    const float* u_T   = (const float*)d_in[2];   // [D-1, A, A]
    const float* lpx   = (const float*)d_in[3];   // [1, D, 1, A]
    float* out = (float*)d_out;

    int B = in_sizes[0] / D_;
    if (B > MAXB) B = MAXB;

    k_prepT<<<(DM1 * A_ + 7) / 8, 256>>>(u_T);
    k_prepS<<<(D_ * A_ + 255) / 256, 256>>>(lpx);
    k_pa1<<<1, 128>>>(u_pa1, out, B * A_, out_size);

    k_forward<<<B, 256>>>(x, out, out_size);
}